// round 9
// baseline (speedup 1.0000x reference)
#include <cuda_runtime.h>
#include <math.h>

// Problem shapes (fixed by the reference)
#define Bsz 4
#define Nn  512
#define Kk  128
#define Ee  768

static constexpr size_t EF_ELEMS    = (size_t)Bsz * Nn * Nn * Kk;   // 134,217,728
static constexpr size_t MERGE_ELEMS = (size_t)Bsz * Nn * Ee;        //   1,572,864
static constexpr size_t MERGE_OFF   = EF_ELEMS;
static constexpr size_t DP_OFF      = EF_ELEMS + MERGE_ELEMS;

static constexpr int N_PROD  = Bsz * Nn;          // 2048 edge blocks
static constexpr int N_ECHNK = Ee / 32;           // 24 e-chunks of 32
static constexpr int N_CONS  = (N_PROD / 32) * N_ECHNK; // 1536 merge blocks

// Scratch: j-summed features [B*N, K] (1 MB, static device array)
__device__ float g_sum[(size_t)N_PROD * Kk];

// ---------------------------------------------------------------------------
// Inline mask-dtype classification (0 = uint8, 1 = int32, 2 = float32).
// ---------------------------------------------------------------------------
__device__ __forceinline__ void classify_masks(const unsigned int* __restrict__ pad,
                                               const unsigned int* __restrict__ node,
                                               int tid, int& mp, int& mn)
{
    __shared__ unsigned int s_hi[2], s_bad[2];
    if (tid < 2) { s_hi[tid] = 0u; s_bad[tid] = 0u; }
    __syncthreads();
    const unsigned int* bufs[2] = { pad, node };
    #pragma unroll
    for (int m = 0; m < 2; m++) {
        unsigned int h = 0u, bf = 0u;
        for (int w = tid; w < 512; w += 128) {     // 2048 bytes
            unsigned int v = bufs[m][w];
            h |= (v & 0xFFFFFF00u);
            if (v != 0u && v != 0x3F800000u) bf = 1u;
        }
        if (h)  atomicOr(&s_hi[m],  h);
        if (bf) atomicOr(&s_bad[m], 1u);
    }
    __syncthreads();
    mp = (s_hi[0] == 0u) ? 1 : (s_bad[0] == 0u ? 2 : 0);
    mn = (s_hi[1] == 0u) ? 1 : (s_bad[1] == 0u ? 2 : 0);
}

__device__ __forceinline__ bool mget(const void* p, int idx, int mode)
{
    if (mode == 1) return ((const int*)p)[idx] != 0;
    if (mode == 2) return ((const float*)p)[idx] != 0.0f;
    return ((const unsigned char*)p)[idx] != 0;
}

__device__ __forceinline__ float ex2f(float x)
{
    float r;
    asm("ex2.approx.ftz.f32 %0, %1;" : "=f"(r) : "f"(x));
    return r;
}

// ---------------------------------------------------------------------------
// Kernel 1: edge stream (round-3 structure + log-space gaussian).
// One block per (b,i); 128 threads; float4 evict-first stores.
// ---------------------------------------------------------------------------
__global__ __launch_bounds__(128, 12) void edge_kernel(
    const float* __restrict__ pos,
    const float* __restrict__ means,
    const float* __restrict__ stds,
    const float* __restrict__ mul_w,
    const float* __restrict__ bias_w,
    const int*   __restrict__ nte,
    const void*  __restrict__ pad_mask,
    const void*  __restrict__ node_mask,
    float* __restrict__ out)
{
    const int bi  = blockIdx.x;       // b*512 + i
    const int b   = bi >> 9;
    const int tid = threadIdx.x;      // 0..127

    __shared__ float sx[Nn];          // x = mul*dist + bias per j
    __shared__ float slg[Nn];         // 0 valid / -1e38 padded (log-space mask)
    __shared__ float red[4][Kk];

    int mp, mn;
    classify_masks((const unsigned int*)pad_mask,
                   (const unsigned int*)node_mask, tid, mp, mn);

    const float pix = pos[(size_t)bi * 3 + 0];
    const float piy = pos[(size_t)bi * 3 + 1];
    const float piz = pos[(size_t)bi * 3 + 2];
    const bool  nmi = mget(node_mask, bi, mn);

    // ---- Phase 1: per-j scalars + delta_pos output ----
    for (int j = tid; j < Nn; j += 128) {
        const size_t pj = ((size_t)b * Nn + j) * 3;
        float dx = pos[pj + 0] - pix;
        float dy = pos[pj + 1] - piy;
        float dz = pos[pj + 2] - piz;
        float d2 = dx * dx + dy * dy + dz * dz;
        float dist = (d2 > 0.0f) ? sqrtf(d2) : 0.0f;
        float inv  = 1.0f / (dist + 1e-5f);

        size_t dpo = DP_OFF + ((size_t)bi * Nn + j) * 3;
        out[dpo + 0] = dx * inv;
        out[dpo + 1] = dy * inv;
        out[dpo + 2] = dz * inv;

        size_t eo = ((size_t)bi * Nn + j) * 2;
        int et0 = nte[eo + 0];
        int et1 = nte[eo + 1];
        if (nmi)                             et0 = 0;
        if (mget(node_mask, b * Nn + j, mn)) et1 = 0;

        float mul  = mul_w[et0]  + mul_w[et1];
        float bias = bias_w[et0] + bias_w[et1];
        sx[j]  = fmaf(mul, dist, bias);
        slg[j] = mget(pad_mask, b * Nn + j, mp) ? -1e38f : 0.0f;
    }
    __syncthreads();

    // ---- Phase 2: log-space gaussian, float4 streamed stores, j-sum ----
    const int jsub = tid >> 5;            // 0..3
    const int k4   = (tid & 31) * 4;

    float mm[4], aa[4], lc[4];
    #pragma unroll
    for (int q = 0; q < 4; q++) {
        float s  = fabsf(stds[k4 + q]) + 0.01f;
        float is = 1.0f / s;
        aa[q] = -0.72134752f * is * is;        // -0.5*log2(e)/s^2
        mm[q] = means[k4 + q];
        lc[q] = -__log2f(2.5066268f * s);      // log2(1/(sqrt(2*pi)*s))
    }

    float acc0 = 0.f, acc1 = 0.f, acc2 = 0.f, acc3 = 0.f;
    const size_t base = (size_t)bi * Nn * Kk;

    #pragma unroll 4
    for (int jb = 0; jb < Nn; jb += 4) {
        const int j = jb + jsub;
        const float x  = sx[j];
        const float sl = slg[j];

        float d0 = x - mm[0], d1 = x - mm[1];
        float d2 = x - mm[2], d3 = x - mm[3];

        float4 v;
        v.x = ex2f(fmaf(aa[0] * d0, d0, lc[0] + sl));
        v.y = ex2f(fmaf(aa[1] * d1, d1, lc[1] + sl));
        v.z = ex2f(fmaf(aa[2] * d2, d2, lc[2] + sl));
        v.w = ex2f(fmaf(aa[3] * d3, d3, lc[3] + sl));

        acc0 += v.x; acc1 += v.y; acc2 += v.z; acc3 += v.w;
        __stcs(reinterpret_cast<float4*>(out + base + (size_t)j * Kk + k4), v);
    }

    red[jsub][k4 + 0] = acc0;
    red[jsub][k4 + 1] = acc1;
    red[jsub][k4 + 2] = acc2;
    red[jsub][k4 + 3] = acc3;
    __syncthreads();

    {
        const int k = tid;   // blockDim == Kk
        float s = red[0][k] + red[1][k] + red[2][k] + red[3][k];
        g_sum[(size_t)bi * Kk + k] = s;
    }
}

// ---------------------------------------------------------------------------
// Kernel 2: merge = g_sum @ proj_w^T + proj_b, masked.
// 1536 blocks of 128 threads; 32x32 tile; K processed in quarters (8.8 KB smem).
// ---------------------------------------------------------------------------
__global__ __launch_bounds__(128) void merge_kernel(
    const float* __restrict__ proj_w,
    const float* __restrict__ proj_b,
    const void* __restrict__ pad_mask,
    const void* __restrict__ node_mask,
    float* __restrict__ out)
{
    __shared__ float As[32][36];
    __shared__ float Bst[32][33];

    const int cid = blockIdx.x;            // 0..1535
    const int g   = cid / N_ECHNK;         // row-group 0..63
    const int ec  = cid % N_ECHNK;         // e-chunk 0..23
    const int row0 = g * 32;
    const int e0   = ec * 32;
    const int tid  = threadIdx.x;

    int mp, mn;
    classify_masks((const unsigned int*)pad_mask,
                   (const unsigned int*)node_mask, tid, mp, mn);

    const int rowg = tid >> 5;    // 0..3 -> rows rowg*8 .. rowg*8+7
    const int eg   = tid & 31;    // output column e0+eg
    const int le = tid & 31;      // staging: e-column
    const int kq = tid >> 5;      // staging: 8-k slab 0..3

    float acc[8] = {};

    #pragma unroll
    for (int q = 0; q < 4; q++) {
        const int k0 = q * 32;

        // Stage B quarter transposed: Bst[k][e] (each thread 8 k of one e).
        {
            const float* pw = proj_w + (size_t)(e0 + le) * Kk + k0 + kq * 8;
            float4 w0 = *(const float4*)(pw + 0);
            float4 w1 = *(const float4*)(pw + 4);
            Bst[kq * 8 + 0][le] = w0.x; Bst[kq * 8 + 1][le] = w0.y;
            Bst[kq * 8 + 2][le] = w0.z; Bst[kq * 8 + 3][le] = w0.w;
            Bst[kq * 8 + 4][le] = w1.x; Bst[kq * 8 + 5][le] = w1.y;
            Bst[kq * 8 + 6][le] = w1.z; Bst[kq * 8 + 7][le] = w1.w;
        }
        // Stage A quarter: As[row][k], coalesced from g_sum.
        for (int idx = tid; idx < 32 * 32; idx += 128) {
            const int row = idx >> 5, kk = idx & 31;
            As[row][kk] = g_sum[(size_t)(row0 + row) * Kk + k0 + kk];
        }
        __syncthreads();

        #pragma unroll
        for (int kb = 0; kb < 32; kb += 4) {
            float b0 = Bst[kb + 0][eg];
            float b1 = Bst[kb + 1][eg];
            float b2 = Bst[kb + 2][eg];
            float b3 = Bst[kb + 3][eg];
            #pragma unroll
            for (int r = 0; r < 8; r++) {
                float4 a = *(const float4*)&As[rowg * 8 + r][kb];
                acc[r] = fmaf(a.x, b0, fmaf(a.y, b1,
                         fmaf(a.z, b2, fmaf(a.w, b3, acc[r]))));
            }
        }
        __syncthreads();
    }

    const float pb = proj_b[e0 + eg];
    #pragma unroll
    for (int r = 0; r < 8; r++) {
        const int grow = row0 + rowg * 8 + r;
        float bm = (mget(pad_mask, grow, mp) || mget(node_mask, grow, mn))
                       ? 0.0f : 1.0f;
        out[MERGE_OFF + (size_t)grow * Ee + e0 + eg] = bm * (acc[r] + pb);
    }
}

// ---------------------------------------------------------------------------
extern "C" void kernel_launch(void* const* d_in, const int* in_sizes, int n_in,
                              void* d_out, int out_size)
{
    const float* pos     = (const float*)d_in[0];
    const float* means   = (const float*)d_in[1];
    const float* stds    = (const float*)d_in[2];
    const float* mul_w   = (const float*)d_in[3];
    const float* bias_w  = (const float*)d_in[4];
    const float* proj_w  = (const float*)d_in[5];
    const float* proj_b  = (const float*)d_in[6];
    const int*   nte     = (const int*)d_in[7];
    const void*  pad_mask  = d_in[8];
    const void*  node_mask = d_in[9];
    float* out = (float*)d_out;

    edge_kernel<<<N_PROD, 128>>>(pos, means, stds, mul_w, bias_w, nte,
                                 pad_mask, node_mask, out);
    merge_kernel<<<N_CONS, 128>>>(proj_w, proj_b, pad_mask, node_mask, out);
}

// round 10
// speedup vs baseline: 1.1089x; 1.1089x over previous
#include <cuda_runtime.h>
#include <math.h>

// Problem shapes (fixed by the reference)
#define Bsz 4
#define Nn  512
#define Kk  128
#define Ee  768

static constexpr size_t EF_ELEMS    = (size_t)Bsz * Nn * Nn * Kk;   // 134,217,728
static constexpr size_t MERGE_ELEMS = (size_t)Bsz * Nn * Ee;        //   1,572,864
static constexpr size_t MERGE_OFF   = EF_ELEMS;
static constexpr size_t DP_OFF      = EF_ELEMS + MERGE_ELEMS;

static constexpr int N_PROD  = Bsz * Nn;          // 2048 producer blocks
static constexpr int GROUP_R = 64;                // rows per merge group
static constexpr int N_GROUP = N_PROD / GROUP_R;  // 32 groups
static constexpr int N_ECHNK = Ee / 64;           // 12 e-chunks of 64
static constexpr int N_CONS  = N_GROUP * N_ECHNK; // 384 consumer blocks

// Scratch: j-summed features [B*N, K] (1 MB) + handshake counters.
__device__ float g_sum[(size_t)N_PROD * Kk];
__device__ int   g_cnt[N_GROUP];    // producers done per group (self-resetting)
__device__ int   g_done[N_GROUP];   // consumers done per group (self-resetting)

// Overlaid branch-local shared storage (producer | consumer).
union SmemU {
    struct {                       // producer: 8 KB
        float sx[Nn];
        float slg[Nn];             // 0 valid / -1e38 padded (log-space mask)
        float red[8][Kk];
    } p;
    struct {                       // consumer: 17.1 KB
        float As[64][33];          // rows x k-quarter
        float Bst[32][68];         // k-quarter x e (transposed)
    } c;
};

// ---------------------------------------------------------------------------
// Inline mask-dtype classification (0 = uint8, 1 = int32, 2 = float32).
// ---------------------------------------------------------------------------
__device__ __forceinline__ void classify_masks(const unsigned int* __restrict__ pad,
                                               const unsigned int* __restrict__ node,
                                               int tid, int& mp, int& mn)
{
    __shared__ unsigned int s_hi[2], s_bad[2];
    if (tid < 2) { s_hi[tid] = 0u; s_bad[tid] = 0u; }
    __syncthreads();
    const unsigned int* bufs[2] = { pad, node };
    #pragma unroll
    for (int m = 0; m < 2; m++) {
        unsigned int h = 0u, bf = 0u;
        for (int w = tid; w < 512; w += 256) {     // 2048 bytes
            unsigned int v = bufs[m][w];
            h |= (v & 0xFFFFFF00u);
            if (v != 0u && v != 0x3F800000u) bf = 1u;
        }
        if (h)  atomicOr(&s_hi[m],  h);
        if (bf) atomicOr(&s_bad[m], 1u);
    }
    __syncthreads();
    mp = (s_hi[0] == 0u) ? 1 : (s_bad[0] == 0u ? 2 : 0);
    mn = (s_hi[1] == 0u) ? 1 : (s_bad[1] == 0u ? 2 : 0);
}

__device__ __forceinline__ bool mget(const void* p, int idx, int mode)
{
    if (mode == 1) return ((const int*)p)[idx] != 0;
    if (mode == 2) return ((const float*)p)[idx] != 0.0f;
    return ((const unsigned char*)p)[idx] != 0;
}

__device__ __forceinline__ float ex2f(float x)
{
    float r;
    asm("ex2.approx.ftz.f32 %0, %1;" : "=f"(r) : "f"(x));
    return r;
}

// ---------------------------------------------------------------------------
// Fused kernel, 256 threads/block, 6 blocks/SM budget (42 regs).
// bids [0,2048): producers (edge_feature + delta_pos + g_sum).
// bids [2048,2432): consumers (64x64 register-tiled merge GEMM).
// ---------------------------------------------------------------------------
__global__ __launch_bounds__(256, 6) void fused_kernel(
    const float* __restrict__ pos,
    const float* __restrict__ means,
    const float* __restrict__ stds,
    const float* __restrict__ mul_w,
    const float* __restrict__ bias_w,
    const int*   __restrict__ nte,
    const void*  __restrict__ pad_mask,
    const void*  __restrict__ node_mask,
    const float* __restrict__ proj_w,
    const float* __restrict__ proj_b,
    float* __restrict__ out)
{
    __shared__ SmemU sm;
    const int tid = threadIdx.x;   // 0..255

    if (blockIdx.x < N_PROD) {
        // ================= PRODUCER =================
        const int bi = blockIdx.x;       // b*512 + i
        const int b  = bi >> 9;

        int mp, mn;
        classify_masks((const unsigned int*)pad_mask,
                       (const unsigned int*)node_mask, tid, mp, mn);

        const float pix = pos[(size_t)bi * 3 + 0];
        const float piy = pos[(size_t)bi * 3 + 1];
        const float piz = pos[(size_t)bi * 3 + 2];
        const bool  nmi = mget(node_mask, bi, mn);

        // ---- Phase 1: per-j scalars + delta_pos output ----
        for (int j = tid; j < Nn; j += 256) {
            const size_t pj = ((size_t)b * Nn + j) * 3;
            float dx = pos[pj + 0] - pix;
            float dy = pos[pj + 1] - piy;
            float dz = pos[pj + 2] - piz;
            float d2 = dx * dx + dy * dy + dz * dz;
            float dist = (d2 > 0.0f) ? sqrtf(d2) : 0.0f;
            float inv  = 1.0f / (dist + 1e-5f);

            size_t dpo = DP_OFF + ((size_t)bi * Nn + j) * 3;
            out[dpo + 0] = dx * inv;
            out[dpo + 1] = dy * inv;
            out[dpo + 2] = dz * inv;

            size_t eo = ((size_t)bi * Nn + j) * 2;
            int et0 = nte[eo + 0];
            int et1 = nte[eo + 1];
            if (nmi)                             et0 = 0;
            if (mget(node_mask, b * Nn + j, mn)) et1 = 0;

            float mul  = mul_w[et0]  + mul_w[et1];
            float bias = bias_w[et0] + bias_w[et1];
            sm.p.sx[j]  = fmaf(mul, dist, bias);
            sm.p.slg[j] = mget(pad_mask, b * Nn + j, mp) ? -1e38f : 0.0f;
        }
        __syncthreads();

        // ---- Phase 2: log-space gaussian, float4 streamed stores, j-sum ----
        const int jsub = tid >> 5;            // 0..7
        const int k4   = (tid & 31) * 4;      // this thread's 4 k-values

        float mm[4], aa[4], lc[4];
        #pragma unroll
        for (int q = 0; q < 4; q++) {
            float s  = fabsf(stds[k4 + q]) + 0.01f;
            float is = 1.0f / s;
            aa[q] = -0.72134752f * is * is;        // -0.5*log2(e)/s^2
            mm[q] = means[k4 + q];
            lc[q] = -__log2f(2.5066268f * s);      // log2(1/(sqrt(2*pi)*s))
        }

        float acc0 = 0.f, acc1 = 0.f, acc2 = 0.f, acc3 = 0.f;
        const size_t base = (size_t)bi * Nn * Kk;

        #pragma unroll 4
        for (int jb = 0; jb < Nn; jb += 8) {
            const int j = jb + jsub;
            const float x  = sm.p.sx[j];
            const float sl = sm.p.slg[j];

            float d0 = x - mm[0], d1 = x - mm[1];
            float d2 = x - mm[2], d3 = x - mm[3];

            float4 v;
            v.x = ex2f(fmaf(aa[0] * d0, d0, lc[0] + sl));
            v.y = ex2f(fmaf(aa[1] * d1, d1, lc[1] + sl));
            v.z = ex2f(fmaf(aa[2] * d2, d2, lc[2] + sl));
            v.w = ex2f(fmaf(aa[3] * d3, d3, lc[3] + sl));

            acc0 += v.x; acc1 += v.y; acc2 += v.z; acc3 += v.w;
            __stcs(reinterpret_cast<float4*>(out + base + (size_t)j * Kk + k4), v);
        }

        sm.p.red[jsub][k4 + 0] = acc0;
        sm.p.red[jsub][k4 + 1] = acc1;
        sm.p.red[jsub][k4 + 2] = acc2;
        sm.p.red[jsub][k4 + 3] = acc3;
        __syncthreads();

        if (tid < Kk) {
            float s = 0.f;
            #pragma unroll
            for (int r = 0; r < 8; r++) s += sm.p.red[r][tid];
            g_sum[(size_t)bi * Kk + tid] = s;
        }
        __syncthreads();

        if (tid == 0) {
            __threadfence();                       // release g_sum row
            atomicAdd(&g_cnt[bi >> 6], 1);
        }
    } else {
        // ========= CONSUMER: 64x64 merge tile, 4x4 regs/thread =========
        const int cid = blockIdx.x - N_PROD;   // 0..383
        const int g   = cid / N_ECHNK;         // group 0..31
        const int ec  = cid % N_ECHNK;         // e-chunk 0..11
        const int row0 = g * GROUP_R;
        const int e0   = ec * 64;

        int mp, mn;
        classify_masks((const unsigned int*)pad_mask,
                       (const unsigned int*)node_mask, tid, mp, mn);

        const int tx = tid & 15;      // e-quad: columns e0 + tx*4 .. +3
        const int ty = tid >> 4;      // row-quad: rows row0 + ty*4 .. +3

        // Wait until all 64 producer rows of this group are published.
        if (tid == 0) {
            volatile int* c = &g_cnt[g];
            while (*c < GROUP_R) __nanosleep(1024);
        }
        __syncthreads();
        __threadfence();   // acquire

        float acc[4][4] = {};
        const int le = tid & 63;      // staging: e-column
        const int kq = tid >> 6;      // staging: 8-k slab 0..3

        #pragma unroll
        for (int q = 0; q < 4; q++) {
            const int k0 = q * 32;

            // Stage B quarter transposed: Bst[k][e] (thread: 8 k of one e).
            {
                const float* pw = proj_w + (size_t)(e0 + le) * Kk + k0 + kq * 8;
                float4 w0 = *(const float4*)(pw + 0);
                float4 w1 = *(const float4*)(pw + 4);
                sm.c.Bst[kq * 8 + 0][le] = w0.x; sm.c.Bst[kq * 8 + 1][le] = w0.y;
                sm.c.Bst[kq * 8 + 2][le] = w0.z; sm.c.Bst[kq * 8 + 3][le] = w0.w;
                sm.c.Bst[kq * 8 + 4][le] = w1.x; sm.c.Bst[kq * 8 + 5][le] = w1.y;
                sm.c.Bst[kq * 8 + 6][le] = w1.z; sm.c.Bst[kq * 8 + 7][le] = w1.w;
            }
            // Stage A quarter: As[row][k], coalesced from g_sum.
            for (int idx = tid; idx < 64 * 32; idx += 256) {
                const int row = idx >> 5, kk = idx & 31;
                sm.c.As[row][kk] = g_sum[(size_t)(row0 + row) * Kk + k0 + kk];
            }
            __syncthreads();

            #pragma unroll 8
            for (int kb = 0; kb < 32; kb++) {
                float4 b4 = *(const float4*)&sm.c.Bst[kb][tx * 4];
                float a0 = sm.c.As[ty * 4 + 0][kb];
                float a1 = sm.c.As[ty * 4 + 1][kb];
                float a2 = sm.c.As[ty * 4 + 2][kb];
                float a3 = sm.c.As[ty * 4 + 3][kb];
                acc[0][0] = fmaf(a0, b4.x, acc[0][0]);
                acc[0][1] = fmaf(a0, b4.y, acc[0][1]);
                acc[0][2] = fmaf(a0, b4.z, acc[0][2]);
                acc[0][3] = fmaf(a0, b4.w, acc[0][3]);
                acc[1][0] = fmaf(a1, b4.x, acc[1][0]);
                acc[1][1] = fmaf(a1, b4.y, acc[1][1]);
                acc[1][2] = fmaf(a1, b4.z, acc[1][2]);
                acc[1][3] = fmaf(a1, b4.w, acc[1][3]);
                acc[2][0] = fmaf(a2, b4.x, acc[2][0]);
                acc[2][1] = fmaf(a2, b4.y, acc[2][1]);
                acc[2][2] = fmaf(a2, b4.z, acc[2][2]);
                acc[2][3] = fmaf(a2, b4.w, acc[2][3]);
                acc[3][0] = fmaf(a3, b4.x, acc[3][0]);
                acc[3][1] = fmaf(a3, b4.y, acc[3][1]);
                acc[3][2] = fmaf(a3, b4.z, acc[3][2]);
                acc[3][3] = fmaf(a3, b4.w, acc[3][3]);
            }
            __syncthreads();
        }

        // Output: 4 rows x float4 of e, bias + mask fused.
        float4 pb = *(const float4*)(proj_b + e0 + tx * 4);
        #pragma unroll
        for (int r = 0; r < 4; r++) {
            const int grow = row0 + ty * 4 + r;
            float bm = (mget(pad_mask, grow, mp) || mget(node_mask, grow, mn))
                           ? 0.0f : 1.0f;
            float4 v;
            v.x = bm * (acc[r][0] + pb.x);
            v.y = bm * (acc[r][1] + pb.y);
            v.z = bm * (acc[r][2] + pb.z);
            v.w = bm * (acc[r][3] + pb.w);
            *reinterpret_cast<float4*>(out + MERGE_OFF + (size_t)grow * Ee
                                       + e0 + tx * 4) = v;
        }

        // Last consumer of this group resets counters for the next replay.
        __syncthreads();
        if (tid == 0) {
            int d = atomicAdd(&g_done[g], 1);
            if (d == N_ECHNK - 1) {
                g_cnt[g]  = 0;
                g_done[g] = 0;
                __threadfence();
            }
        }
    }
}

// ---------------------------------------------------------------------------
extern "C" void kernel_launch(void* const* d_in, const int* in_sizes, int n_in,
                              void* d_out, int out_size)
{
    const float* pos     = (const float*)d_in[0];
    const float* means   = (const float*)d_in[1];
    const float* stds    = (const float*)d_in[2];
    const float* mul_w   = (const float*)d_in[3];
    const float* bias_w  = (const float*)d_in[4];
    const float* proj_w  = (const float*)d_in[5];
    const float* proj_b  = (const float*)d_in[6];
    const int*   nte     = (const int*)d_in[7];
    const void*  pad_mask  = d_in[8];
    const void*  node_mask = d_in[9];
    float* out = (float*)d_out;

    fused_kernel<<<N_PROD + N_CONS, 256>>>(pos, means, stds, mul_w, bias_w, nte,
                                           pad_mask, node_mask, proj_w, proj_b, out);
}